// round 15
// baseline (speedup 1.0000x reference)
#include <cuda_runtime.h>
#include <cstdint>

// IntensityTransformation: out_k[b,c,h,w] = tf_k[b,c, round(255*img[b,c,h,w])]
// B=8, C=3, H=W=1024, LUT=256. Output = concat(out1, out2, out3), fp32.
//
// R15: R14 base (best kernel 62.56us) + two zero-structural-cost levers:
//  (a) prefetch-1: next iteration's __ldcs issued before this iteration's
//      lookups/stores -> per-warp read MLP 2 instead of 1.
//  (b) stream rotation: (LUT, output) pairs permuted by plane%3 so CTAs
//      don't store to the three output streams in chip-wide lockstep order.

static constexpr int PLANES = 24;                    // B*C
static constexpr long long PLANE = 1024LL * 1024LL;  // floats per plane
static constexpr int LUT = 256;

__device__ __forceinline__ void stwt128(float4* p, float4 v) {
    asm volatile("st.global.wt.v4.f32 [%0], {%1,%2,%3,%4};"
                 :: "l"(p), "f"(v.x), "f"(v.y), "f"(v.z), "f"(v.w)
                 : "memory");
}

__global__ __launch_bounds__(256)
void intensity_lut_kernel(const float* __restrict__ img,
                          const float* __restrict__ tf1,
                          const float* __restrict__ tf2,
                          const float* __restrict__ tf3,
                          float* __restrict__ out)
{
    __shared__ float s1[LUT];
    __shared__ float s2[LUT];
    __shared__ float s3[LUT];

    const int plane = blockIdx.y;          // 0..23
    const int t = threadIdx.x;             // blockDim.x == 256
    const int rot = plane % 3;             // per-plane stream rotation

    // Rotated (LUT, output) pairing: slot j handles logical stream (rot+j)%3.
    const float* const tfs[3] = {tf1, tf2, tf3};
    const int p0 = rot, p1 = (rot + 1) % 3, p2 = (rot + 2) % 3;

    s1[t] = tfs[p0][plane * LUT + t];
    s2[t] = tfs[p1][plane * LUT + t];
    s3[t] = tfs[p2][plane * LUT + t];
    __syncthreads();

    const long long base = (long long)plane * PLANE;
    const float4* __restrict__ in4 = reinterpret_cast<const float4*>(img + base);
    float4* __restrict__ o1 = reinterpret_cast<float4*>(out + (long long)p0 * PLANES * PLANE + base);
    float4* __restrict__ o2 = reinterpret_cast<float4*>(out + (long long)p1 * PLANES * PLANE + base);
    float4* __restrict__ o3 = reinterpret_cast<float4*>(out + (long long)p2 * PLANES * PLANE + base);

    const int n4 = (int)(PLANE / 4);       // 262144 float4 per plane
    const int stride = gridDim.x * blockDim.x;

    int i = blockIdx.x * blockDim.x + t;
    if (i >= n4) return;

    // Prefetch-1 pipeline: next load is in flight while current is processed.
    float4 v = __ldcs(&in4[i]);
    while (true) {
        const int inext = i + stride;
        float4 vn;
        const bool has_next = (inext < n4);
        if (has_next) vn = __ldcs(&in4[inext]);   // MLP=2: issued before stores

        const int i0 = __float2int_rn(255.0f * v.x);
        const int i1 = __float2int_rn(255.0f * v.y);
        const int i2 = __float2int_rn(255.0f * v.z);
        const int i3 = __float2int_rn(255.0f * v.w);

        stwt128(&o1[i], make_float4(s1[i0], s1[i1], s1[i2], s1[i3]));
        stwt128(&o2[i], make_float4(s2[i0], s2[i1], s2[i2], s2[i3]));
        stwt128(&o3[i], make_float4(s3[i0], s3[i1], s3[i2], s3[i3]));

        if (!has_next) break;
        v = vn;
        i = inext;
    }
}

extern "C" void kernel_launch(void* const* d_in, const int* in_sizes, int n_in,
                              void* d_out, int out_size)
{
    const float* img = (const float*)d_in[0];
    const float* tf1 = (const float*)d_in[1];
    const float* tf2 = (const float*)d_in[2];
    const float* tf3 = (const float*)d_in[3];
    float* out = (float*)d_out;

    dim3 grid(256, PLANES);   // 6144 CTAs, best-performing shape
    dim3 block(256);
    intensity_lut_kernel<<<grid, block>>>(img, tf1, tf2, tf3, out);
}

// round 16
// speedup vs baseline: 1.0654x; 1.0654x over previous
#include <cuda_runtime.h>
#include <cstdint>

// IntensityTransformation: out_k[b,c,h,w] = tf_k[b,c, round(255*img[b,c,h,w])]
// B=8, C=3, H=W=1024, LUT=256. Output = concat(out1, out2, out3), fp32.
//
// FINAL (R12 revert): pure HBM-streaming kernel at the measured DRAM
// efficiency floor (~6.4 TB/s effective, 80% of spec) for a 1R:3W mix.
// Per-plane 3x256 LUT in smem; float4 load + 3x float4 stores per thread-
// iteration; __ldcs on the read-once img stream, default-policy stores.
// Seven structural variants (TMA bulk stores, v8.f32, occupancy sweeps,
// all L2 policy combos, prefetch pipelining) all landed within noise of
// this kernel or regressed — the limiter is DRAM R/W scheduling, not SMs.

static constexpr int PLANES = 24;                    // B*C
static constexpr long long PLANE = 1024LL * 1024LL;  // floats per plane
static constexpr int LUT = 256;

__global__ __launch_bounds__(256)
void intensity_lut_kernel(const float* __restrict__ img,
                          const float* __restrict__ tf1,
                          const float* __restrict__ tf2,
                          const float* __restrict__ tf3,
                          float* __restrict__ out)
{
    __shared__ float s1[LUT];
    __shared__ float s2[LUT];
    __shared__ float s3[LUT];

    const int plane = blockIdx.y;          // 0..23
    const int t = threadIdx.x;             // blockDim.x == 256

    // Stage this plane's three LUTs into shared memory.
    s1[t] = tf1[plane * LUT + t];
    s2[t] = tf2[plane * LUT + t];
    s3[t] = tf3[plane * LUT + t];
    __syncthreads();

    const long long base = (long long)plane * PLANE;
    const float4* __restrict__ in4 = reinterpret_cast<const float4*>(img + base);
    float4* __restrict__ o1 = reinterpret_cast<float4*>(out + base);
    float4* __restrict__ o2 = reinterpret_cast<float4*>(out + (long long)PLANES * PLANE + base);
    float4* __restrict__ o3 = reinterpret_cast<float4*>(out + 2LL * PLANES * PLANE + base);

    const int n4 = (int)(PLANE / 4);       // 262144 float4 per plane
    const int stride = gridDim.x * blockDim.x;

    for (int i = blockIdx.x * blockDim.x + t; i < n4; i += stride) {
        float4 v = __ldcs(&in4[i]);        // evict-first: don't pollute L2
        int i0 = __float2int_rn(255.0f * v.x);
        int i1 = __float2int_rn(255.0f * v.y);
        int i2 = __float2int_rn(255.0f * v.z);
        int i3 = __float2int_rn(255.0f * v.w);

        float4 r1 = make_float4(s1[i0], s1[i1], s1[i2], s1[i3]);
        float4 r2 = make_float4(s2[i0], s2[i1], s2[i2], s2[i3]);
        float4 r3 = make_float4(s3[i0], s3[i1], s3[i2], s3[i3]);

        o1[i] = r1;   // default policy stores
        o2[i] = r2;
        o3[i] = r3;
    }
}

extern "C" void kernel_launch(void* const* d_in, const int* in_sizes, int n_in,
                              void* d_out, int out_size)
{
    const float* img = (const float*)d_in[0];
    const float* tf1 = (const float*)d_in[1];
    const float* tf2 = (const float*)d_in[2];
    const float* tf3 = (const float*)d_in[3];
    float* out = (float*)d_out;

    dim3 grid(256, PLANES);   // 6144 CTAs
    dim3 block(256);
    intensity_lut_kernel<<<grid, block>>>(img, tf1, tf2, tf3, out);
}